// round 13
// baseline (speedup 1.0000x reference)
#include <cuda_runtime.h>
#include <cstdint>

// ---------------------------------------------------------------------------
// TreeLSTMCell fused as ONE GEMM + epilogue.
//
//   A[n, 0:256]    = x[n] * x_mask[n]
//   A[n, 256:1536] = neighbour_h[n] (flattened 5*256)
//   W[k, c] packed:
//     c in [0,768):    k<256 -> W_iou_in[k,c]        else W_aggr_iou[k-256,c]
//     c in [768,2048): j=c-768
//                      k<256 -> 2*W_f_in[k, j%256]   else W_aggr_f[k-256, j]
//   P = A @ W   (tf32 tensor cores, fp32 accumulate)
//   Epilogue: add biases (mask-scaled where needed), gates, child reduction.
// ---------------------------------------------------------------------------

#define M_NODES 50000
#define K_DIM   1536
#define N_OUT   2048
#define HDIM    256
#define NCH     5

#define BM 128
#define BN 128
#define BK 16
#define SA 136   // padded smem stride (16-float skew -> conflict-free frag LDS)
#define SB 136

// Scratch (allocation-free rule: __device__ globals)
__device__ float g_Wp[K_DIM * N_OUT];                     // 12.6 MB packed weights (tf32-rounded)
__device__ float g_P[(size_t)M_NODES * N_OUT];            // 409.6 MB pre-activation scratch

// ---------------------------------------------------------------------------
__device__ __forceinline__ uint32_t f2tf32(float f) {
    uint32_t u;
    asm("cvt.rna.tf32.f32 %0, %1;" : "=r"(u) : "f"(f));
    return u;
}

// ---------------------------------------------------------------------------
__global__ void pack_w_kernel(const float* __restrict__ Wiou,
                              const float* __restrict__ Wf,
                              const float* __restrict__ Waiou,
                              const float* __restrict__ Waf)
{
    int idx = blockIdx.x * blockDim.x + threadIdx.x;
    if (idx >= K_DIM * N_OUT) return;
    int k = idx >> 11;       // / 2048
    int c = idx & 2047;
    float v;
    if (c < 768) {
        v = (k < 256) ? Wiou[k * 768 + c] : Waiou[(k - 256) * 768 + c];
    } else {
        int j = c - 768;
        v = (k < 256) ? 2.0f * Wf[k * 256 + (j & 255)]
                      : Waf[(k - 256) * 1280 + j];
    }
    g_Wp[idx] = __uint_as_float(f2tf32(v));   // pre-round B to tf32
}

// ---------------------------------------------------------------------------
__device__ __forceinline__ void load_tileA(const float* __restrict__ x,
                                           const float* __restrict__ x_mask,
                                           const float* __restrict__ nh,
                                           int rowbase, int k0, int tid,
                                           float4* ra)
{
#pragma unroll
    for (int i = 0; i < 2; i++) {
        int idx = i * 256 + tid;
        int r   = idx >> 2;
        int gk  = k0 + (idx & 3) * 4;
        int row = rowbase + r;
        float4 v = make_float4(0.f, 0.f, 0.f, 0.f);
        if (row < M_NODES) {
            if (gk < 256) {
                v = *(const float4*)(x + (size_t)row * 256 + gk);
                float m = x_mask[row];
                v.x *= m; v.y *= m; v.z *= m; v.w *= m;
            } else {
                v = *(const float4*)(nh + (size_t)row * 1280 + (gk - 256));
            }
        }
        ra[i] = v;
    }
}

__device__ __forceinline__ void load_tileB(int colbase, int k0, int tid, float4* rb)
{
#pragma unroll
    for (int i = 0; i < 2; i++) {
        int idx = i * 256 + tid;
        int kl  = idx >> 5;
        int n4  = (idx & 31) * 4;
        rb[i] = *(const float4*)(g_Wp + (size_t)(k0 + kl) * N_OUT + colbase + n4);
    }
}

__device__ __forceinline__ void store_tileA(float* sa, int tid, const float4* ra)
{
#pragma unroll
    for (int i = 0; i < 2; i++) {
        int idx = i * 256 + tid;
        int r   = idx >> 2;
        int kl  = (idx & 3) * 4;
        sa[(kl + 0) * SA + r] = __uint_as_float(f2tf32(ra[i].x));
        sa[(kl + 1) * SA + r] = __uint_as_float(f2tf32(ra[i].y));
        sa[(kl + 2) * SA + r] = __uint_as_float(f2tf32(ra[i].z));
        sa[(kl + 3) * SA + r] = __uint_as_float(f2tf32(ra[i].w));
    }
}

__device__ __forceinline__ void store_tileB(float* sb, int tid, const float4* rb)
{
#pragma unroll
    for (int i = 0; i < 2; i++) {
        int idx = i * 256 + tid;
        int kl  = idx >> 5;
        int n4  = (idx & 31) * 4;
        *(float4*)(sb + kl * SB + n4) = rb[i];
    }
}

// ---------------------------------------------------------------------------
__global__ __launch_bounds__(256, 2)
void gemm_tf32_kernel(const float* __restrict__ x,
                      const float* __restrict__ x_mask,
                      const float* __restrict__ nh)
{
    __shared__ float s_a[2][BK * SA];
    __shared__ float s_b[2][BK * SB];

    const int tid  = threadIdx.x;
    const int warp = tid >> 5;
    const int lane = tid & 31;
    const int gid  = lane >> 2;   // group id 0..7
    const int tig  = lane & 3;    // thread-in-group 0..3
    const int wm   = warp & 1;    // 2 warps over M (64 each)
    const int wn   = warp >> 1;   // 4 warps over N (32 each)

    const int rowbase = blockIdx.y * BM;
    const int colbase = blockIdx.x * BN;   // col tiles fastest -> A-tile L2 reuse

    float acc[4][4][4];
#pragma unroll
    for (int a = 0; a < 4; a++)
#pragma unroll
        for (int b = 0; b < 4; b++)
#pragma unroll
            for (int q = 0; q < 4; q++) acc[a][b][q] = 0.f;

    float4 ra[2], rb[2];

    // prologue: tile 0
    load_tileA(x, x_mask, nh, rowbase, 0, tid, ra);
    load_tileB(colbase, 0, tid, rb);
    store_tileA(s_a[0], tid, ra);
    store_tileB(s_b[0], tid, rb);
    __syncthreads();

    const int NT = K_DIM / BK;   // 96
    for (int kt = 0; kt < NT; kt++) {
        const int cur = kt & 1;
        if (kt + 1 < NT) {
            load_tileA(x, x_mask, nh, rowbase, (kt + 1) * BK, tid, ra);
            load_tileB(colbase, (kt + 1) * BK, tid, rb);
        }
        const float* sa = s_a[cur];
        const float* sb = s_b[cur];

#pragma unroll
        for (int ks = 0; ks < 2; ks++) {
            const int kk = ks * 8;
            uint32_t af[4][4], bf[4][2];
#pragma unroll
            for (int mt = 0; mt < 4; mt++) {
                int r0 = wm * 64 + mt * 16 + gid;
                const float* b0 = sa + (kk + tig) * SA;
                const float* b1 = sa + (kk + tig + 4) * SA;
                af[mt][0] = __float_as_uint(b0[r0]);
                af[mt][1] = __float_as_uint(b0[r0 + 8]);
                af[mt][2] = __float_as_uint(b1[r0]);
                af[mt][3] = __float_as_uint(b1[r0 + 8]);
            }
#pragma unroll
            for (int nt = 0; nt < 4; nt++) {
                int c0 = wn * 32 + nt * 8 + gid;
                bf[nt][0] = __float_as_uint(sb[(kk + tig) * SB + c0]);
                bf[nt][1] = __float_as_uint(sb[(kk + tig + 4) * SB + c0]);
            }
#pragma unroll
            for (int mt = 0; mt < 4; mt++)
#pragma unroll
                for (int nt = 0; nt < 4; nt++) {
                    asm volatile(
                        "mma.sync.aligned.m16n8k8.row.col.f32.tf32.tf32.f32 "
                        "{%0,%1,%2,%3}, {%4,%5,%6,%7}, {%8,%9}, {%0,%1,%2,%3};\n"
                        : "+f"(acc[mt][nt][0]), "+f"(acc[mt][nt][1]),
                          "+f"(acc[mt][nt][2]), "+f"(acc[mt][nt][3])
                        : "r"(af[mt][0]), "r"(af[mt][1]),
                          "r"(af[mt][2]), "r"(af[mt][3]),
                          "r"(bf[nt][0]), "r"(bf[nt][1]));
                }
        }

        if (kt + 1 < NT) {
            const int nxt = cur ^ 1;
            store_tileA(s_a[nxt], tid, ra);
            store_tileB(s_b[nxt], tid, rb);
            __syncthreads();
        }
    }

    // writeback
#pragma unroll
    for (int mt = 0; mt < 4; mt++) {
        int r0 = rowbase + wm * 64 + mt * 16 + gid;
#pragma unroll
        for (int nt = 0; nt < 4; nt++) {
            int c0 = colbase + wn * 32 + nt * 8 + tig * 2;
            if (r0 < M_NODES)
                *(float2*)(g_P + (size_t)r0 * N_OUT + c0) =
                    make_float2(acc[mt][nt][0], acc[mt][nt][1]);
            if (r0 + 8 < M_NODES)
                *(float2*)(g_P + (size_t)(r0 + 8) * N_OUT + c0) =
                    make_float2(acc[mt][nt][2], acc[mt][nt][3]);
        }
    }
}

// ---------------------------------------------------------------------------
__global__ void epilogue_kernel(const float* __restrict__ x_mask,
                                const float* __restrict__ nc,
                                const float* __restrict__ b_iou_in,
                                const float* __restrict__ b_f_in,
                                const float* __restrict__ b_aggr_iou,
                                const float* __restrict__ b_aggr_f,
                                float* __restrict__ out)
{
    const int n = blockIdx.x;
    const int j = threadIdx.x;
    const float m = x_mask[n];
    const float* row = g_P + (size_t)n * N_OUT;

    float iv = row[j]       + b_aggr_iou[j]       + m * b_iou_in[j];
    float ov = row[256 + j] + b_aggr_iou[256 + j] + m * b_iou_in[256 + j];
    float uv = row[512 + j] + b_aggr_iou[512 + j] + m * b_iou_in[512 + j];
    float fb = 2.0f * m * b_f_in[j];

    float cagg = 0.0f;
#pragma unroll
    for (int ch = 0; ch < NCH; ch++) {
        int o = ch * 256 + j;
        float fg = row[768 + o] + b_aggr_f[o] + fb;
        float f  = 1.0f / (1.0f + expf(-fg));
        cagg += f * nc[(size_t)n * (NCH * 256) + o];
    }

    float ig = 1.0f / (1.0f + expf(-iv));
    float og = 1.0f / (1.0f + expf(-ov));
    float ug = tanhf(uv);
    float c  = ig * ug + cagg;
    float h  = og * tanhf(c);

    out[(size_t)n * HDIM + j] = h;                                    // h block
    out[(size_t)M_NODES * HDIM + (size_t)n * HDIM + j] = c;           // c block
}

// ---------------------------------------------------------------------------
extern "C" void kernel_launch(void* const* d_in, const int* in_sizes, int n_in,
                              void* d_out, int out_size)
{
    const float* x      = (const float*)d_in[0];
    const float* x_mask = (const float*)d_in[1];
    const float* nh     = (const float*)d_in[2];
    const float* nc     = (const float*)d_in[3];
    const float* Wiou   = (const float*)d_in[4];
    const float* biou   = (const float*)d_in[5];
    const float* Wf     = (const float*)d_in[6];
    const float* bf     = (const float*)d_in[7];
    const float* Waiou  = (const float*)d_in[8];
    const float* baiou  = (const float*)d_in[9];
    const float* Waf    = (const float*)d_in[10];
    const float* baf    = (const float*)d_in[11];
    float* out = (float*)d_out;

    pack_w_kernel<<<(K_DIM * N_OUT + 255) / 256, 256>>>(Wiou, Wf, Waiou, Waf);

    dim3 grid(N_OUT / BN, (M_NODES + BM - 1) / BM);   // col tiles fastest
    gemm_tf32_kernel<<<grid, 256>>>(x, x_mask, nh);

    epilogue_kernel<<<M_NODES, 256>>>(x_mask, nc, biou, bf, baiou, baf, out);
}

// round 14
// speedup vs baseline: 1.0016x; 1.0016x over previous
#include <cuda_runtime.h>
#include <cstdint>

// ---------------------------------------------------------------------------
// TreeLSTMCell fused as ONE GEMM + epilogue.
//
//   A[n, 0:256]    = x[n] * x_mask[n]
//   A[n, 256:1536] = neighbour_h[n] (flattened 5*256)
//   W[k, c] packed:
//     c in [0,768):    k<256 -> W_iou_in[k,c]        else W_aggr_iou[k-256,c]
//     c in [768,2048): j=c-768
//                      k<256 -> 2*W_f_in[k, j%256]   else W_aggr_f[k-256, j]
//   P = A @ W   (tf32 tensor cores, fp32 accumulate)
//   Epilogue: add biases (mask-scaled where needed), gates, child reduction.
// ---------------------------------------------------------------------------

#define M_NODES 50000
#define K_DIM   1536
#define N_OUT   2048
#define HDIM    256
#define NCH     5

#define BM 128
#define BN 128
#define BK 16
#define SA 136   // padded smem stride (16-float skew -> conflict-free frag LDS)
#define SB 136

// Scratch (allocation-free rule: __device__ globals)
__device__ float g_Wp[K_DIM * N_OUT];                     // 12.6 MB packed weights (tf32-rounded)
__device__ float g_P[(size_t)M_NODES * N_OUT];            // 409.6 MB pre-activation scratch

// ---------------------------------------------------------------------------
__device__ __forceinline__ uint32_t f2tf32(float f) {
    uint32_t u;
    asm("cvt.rna.tf32.f32 %0, %1;" : "=r"(u) : "f"(f));
    return u;
}

// ---------------------------------------------------------------------------
__global__ void pack_w_kernel(const float* __restrict__ Wiou,
                              const float* __restrict__ Wf,
                              const float* __restrict__ Waiou,
                              const float* __restrict__ Waf)
{
    int idx = blockIdx.x * blockDim.x + threadIdx.x;
    if (idx >= K_DIM * N_OUT) return;
    int k = idx >> 11;       // / 2048
    int c = idx & 2047;
    float v;
    if (c < 768) {
        v = (k < 256) ? Wiou[k * 768 + c] : Waiou[(k - 256) * 768 + c];
    } else {
        int j = c - 768;
        v = (k < 256) ? 2.0f * Wf[k * 256 + (j & 255)]
                      : Waf[(k - 256) * 1280 + j];
    }
    g_Wp[idx] = __uint_as_float(f2tf32(v));   // pre-round B to tf32
}

// ---------------------------------------------------------------------------
__device__ __forceinline__ void load_tileA(const float* __restrict__ x,
                                           const float* __restrict__ x_mask,
                                           const float* __restrict__ nh,
                                           int rowbase, int k0, int tid,
                                           float4* ra)
{
#pragma unroll
    for (int i = 0; i < 2; i++) {
        int idx = i * 256 + tid;
        int r   = idx >> 2;
        int gk  = k0 + (idx & 3) * 4;
        int row = rowbase + r;
        float4 v = make_float4(0.f, 0.f, 0.f, 0.f);
        if (row < M_NODES) {
            if (gk < 256) {
                v = *(const float4*)(x + (size_t)row * 256 + gk);
                float m = x_mask[row];
                v.x *= m; v.y *= m; v.z *= m; v.w *= m;
            } else {
                v = *(const float4*)(nh + (size_t)row * 1280 + (gk - 256));
            }
        }
        ra[i] = v;
    }
}

__device__ __forceinline__ void load_tileB(int colbase, int k0, int tid, float4* rb)
{
#pragma unroll
    for (int i = 0; i < 2; i++) {
        int idx = i * 256 + tid;
        int kl  = idx >> 5;
        int n4  = (idx & 31) * 4;
        rb[i] = *(const float4*)(g_Wp + (size_t)(k0 + kl) * N_OUT + colbase + n4);
    }
}

__device__ __forceinline__ void store_tileA(float* sa, int tid, const float4* ra)
{
#pragma unroll
    for (int i = 0; i < 2; i++) {
        int idx = i * 256 + tid;
        int r   = idx >> 2;
        int kl  = (idx & 3) * 4;
        sa[(kl + 0) * SA + r] = __uint_as_float(f2tf32(ra[i].x));
        sa[(kl + 1) * SA + r] = __uint_as_float(f2tf32(ra[i].y));
        sa[(kl + 2) * SA + r] = __uint_as_float(f2tf32(ra[i].z));
        sa[(kl + 3) * SA + r] = __uint_as_float(f2tf32(ra[i].w));
    }
}

__device__ __forceinline__ void store_tileB(float* sb, int tid, const float4* rb)
{
#pragma unroll
    for (int i = 0; i < 2; i++) {
        int idx = i * 256 + tid;
        int kl  = idx >> 5;
        int n4  = (idx & 31) * 4;
        *(float4*)(sb + kl * SB + n4) = rb[i];
    }
}

// ---------------------------------------------------------------------------
__global__ __launch_bounds__(256, 2)
void gemm_tf32_kernel(const float* __restrict__ x,
                      const float* __restrict__ x_mask,
                      const float* __restrict__ nh)
{
    __shared__ float s_a[2][BK * SA];
    __shared__ float s_b[2][BK * SB];

    const int tid  = threadIdx.x;
    const int warp = tid >> 5;
    const int lane = tid & 31;
    const int gid  = lane >> 2;   // group id 0..7
    const int tig  = lane & 3;    // thread-in-group 0..3
    const int wm   = warp & 1;    // 2 warps over M (64 each)
    const int wn   = warp >> 1;   // 4 warps over N (32 each)

    const int rowbase = blockIdx.y * BM;
    const int colbase = blockIdx.x * BN;   // col tiles fastest -> A-tile L2 reuse

    float acc[4][4][4];
#pragma unroll
    for (int a = 0; a < 4; a++)
#pragma unroll
        for (int b = 0; b < 4; b++)
#pragma unroll
            for (int q = 0; q < 4; q++) acc[a][b][q] = 0.f;

    float4 ra[2], rb[2];

    // prologue: tile 0
    load_tileA(x, x_mask, nh, rowbase, 0, tid, ra);
    load_tileB(colbase, 0, tid, rb);
    store_tileA(s_a[0], tid, ra);
    store_tileB(s_b[0], tid, rb);
    __syncthreads();

    const int NT = K_DIM / BK;   // 96
    for (int kt = 0; kt < NT; kt++) {
        const int cur = kt & 1;
        if (kt + 1 < NT) {
            load_tileA(x, x_mask, nh, rowbase, (kt + 1) * BK, tid, ra);
            load_tileB(colbase, (kt + 1) * BK, tid, rb);
        }
        const float* sa = s_a[cur];
        const float* sb = s_b[cur];

#pragma unroll
        for (int ks = 0; ks < 2; ks++) {
            const int kk = ks * 8;
            uint32_t af[4][4], bf[4][2];
#pragma unroll
            for (int mt = 0; mt < 4; mt++) {
                int r0 = wm * 64 + mt * 16 + gid;
                const float* b0 = sa + (kk + tig) * SA;
                const float* b1 = sa + (kk + tig + 4) * SA;
                af[mt][0] = __float_as_uint(b0[r0]);
                af[mt][1] = __float_as_uint(b0[r0 + 8]);
                af[mt][2] = __float_as_uint(b1[r0]);
                af[mt][3] = __float_as_uint(b1[r0 + 8]);
            }
#pragma unroll
            for (int nt = 0; nt < 4; nt++) {
                int c0 = wn * 32 + nt * 8 + gid;
                bf[nt][0] = __float_as_uint(sb[(kk + tig) * SB + c0]);
                bf[nt][1] = __float_as_uint(sb[(kk + tig + 4) * SB + c0]);
            }
#pragma unroll
            for (int mt = 0; mt < 4; mt++)
#pragma unroll
                for (int nt = 0; nt < 4; nt++) {
                    asm volatile(
                        "mma.sync.aligned.m16n8k8.row.col.f32.tf32.tf32.f32 "
                        "{%0,%1,%2,%3}, {%4,%5,%6,%7}, {%8,%9}, {%0,%1,%2,%3};\n"
                        : "+f"(acc[mt][nt][0]), "+f"(acc[mt][nt][1]),
                          "+f"(acc[mt][nt][2]), "+f"(acc[mt][nt][3])
                        : "r"(af[mt][0]), "r"(af[mt][1]),
                          "r"(af[mt][2]), "r"(af[mt][3]),
                          "r"(bf[nt][0]), "r"(bf[nt][1]));
                }
        }

        if (kt + 1 < NT) {
            const int nxt = cur ^ 1;
            store_tileA(s_a[nxt], tid, ra);
            store_tileB(s_b[nxt], tid, rb);
            __syncthreads();
        }
    }

    // writeback
#pragma unroll
    for (int mt = 0; mt < 4; mt++) {
        int r0 = rowbase + wm * 64 + mt * 16 + gid;
#pragma unroll
        for (int nt = 0; nt < 4; nt++) {
            int c0 = colbase + wn * 32 + nt * 8 + tig * 2;
            if (r0 < M_NODES)
                *(float2*)(g_P + (size_t)r0 * N_OUT + c0) =
                    make_float2(acc[mt][nt][0], acc[mt][nt][1]);
            if (r0 + 8 < M_NODES)
                *(float2*)(g_P + (size_t)(r0 + 8) * N_OUT + c0) =
                    make_float2(acc[mt][nt][2], acc[mt][nt][3]);
        }
    }
}

// ---------------------------------------------------------------------------
__global__ void epilogue_kernel(const float* __restrict__ x_mask,
                                const float* __restrict__ nc,
                                const float* __restrict__ b_iou_in,
                                const float* __restrict__ b_f_in,
                                const float* __restrict__ b_aggr_iou,
                                const float* __restrict__ b_aggr_f,
                                float* __restrict__ out)
{
    const int n = blockIdx.x;
    const int j = threadIdx.x;
    const float m = x_mask[n];
    const float* row = g_P + (size_t)n * N_OUT;

    float iv = row[j]       + b_aggr_iou[j]       + m * b_iou_in[j];
    float ov = row[256 + j] + b_aggr_iou[256 + j] + m * b_iou_in[256 + j];
    float uv = row[512 + j] + b_aggr_iou[512 + j] + m * b_iou_in[512 + j];
    float fb = 2.0f * m * b_f_in[j];

    float cagg = 0.0f;
#pragma unroll
    for (int ch = 0; ch < NCH; ch++) {
        int o = ch * 256 + j;
        float fg = row[768 + o] + b_aggr_f[o] + fb;
        float f  = 1.0f / (1.0f + expf(-fg));
        cagg += f * nc[(size_t)n * (NCH * 256) + o];
    }

    float ig = 1.0f / (1.0f + expf(-iv));
    float og = 1.0f / (1.0f + expf(-ov));
    float ug = tanhf(uv);
    float c  = ig * ug + cagg;
    float h  = og * tanhf(c);

    out[(size_t)n * HDIM + j] = h;                                    // h block
    out[(size_t)M_NODES * HDIM + (size_t)n * HDIM + j] = c;           // c block
}

// ---------------------------------------------------------------------------
extern "C" void kernel_launch(void* const* d_in, const int* in_sizes, int n_in,
                              void* d_out, int out_size)
{
    const float* x      = (const float*)d_in[0];
    const float* x_mask = (const float*)d_in[1];
    const float* nh     = (const float*)d_in[2];
    const float* nc     = (const float*)d_in[3];
    const float* Wiou   = (const float*)d_in[4];
    const float* biou   = (const float*)d_in[5];
    const float* Wf     = (const float*)d_in[6];
    const float* bf     = (const float*)d_in[7];
    const float* Waiou  = (const float*)d_in[8];
    const float* baiou  = (const float*)d_in[9];
    const float* Waf    = (const float*)d_in[10];
    const float* baf    = (const float*)d_in[11];
    float* out = (float*)d_out;

    pack_w_kernel<<<(K_DIM * N_OUT + 255) / 256, 256>>>(Wiou, Wf, Waiou, Waf);

    dim3 grid(N_OUT / BN, (M_NODES + BM - 1) / BM);   // col tiles fastest
    gemm_tf32_kernel<<<grid, 256>>>(x, x_mask, nh);

    epilogue_kernel<<<M_NODES, 256>>>(x_mask, nc, biou, bf, baiou, baf, out);
}

// round 15
// speedup vs baseline: 1.0019x; 1.0003x over previous
#include <cuda_runtime.h>
#include <cstdint>

// ---------------------------------------------------------------------------
// TreeLSTMCell fused as ONE GEMM + epilogue.
//
//   A[n, 0:256]    = x[n] * x_mask[n]
//   A[n, 256:1536] = neighbour_h[n] (flattened 5*256)
//   W[k, c] packed:
//     c in [0,768):    k<256 -> W_iou_in[k,c]        else W_aggr_iou[k-256,c]
//     c in [768,2048): j=c-768
//                      k<256 -> 2*W_f_in[k, j%256]   else W_aggr_f[k-256, j]
//   P = A @ W   (tf32 tensor cores, fp32 accumulate)
//   Epilogue: add biases (mask-scaled where needed), gates, child reduction.
// ---------------------------------------------------------------------------

#define M_NODES 50000
#define K_DIM   1536
#define N_OUT   2048
#define HDIM    256
#define NCH     5

#define BM 128
#define BN 128
#define BK 16
#define SA 136   // padded smem stride (16-float skew -> conflict-free frag LDS)
#define SB 136

// Scratch (allocation-free rule: __device__ globals)
__device__ float g_Wp[K_DIM * N_OUT];                     // 12.6 MB packed weights (tf32-rounded)
__device__ float g_P[(size_t)M_NODES * N_OUT];            // 409.6 MB pre-activation scratch

// ---------------------------------------------------------------------------
__device__ __forceinline__ uint32_t f2tf32(float f) {
    uint32_t u;
    asm("cvt.rna.tf32.f32 %0, %1;" : "=r"(u) : "f"(f));
    return u;
}

// ---------------------------------------------------------------------------
__global__ void pack_w_kernel(const float* __restrict__ Wiou,
                              const float* __restrict__ Wf,
                              const float* __restrict__ Waiou,
                              const float* __restrict__ Waf)
{
    int idx = blockIdx.x * blockDim.x + threadIdx.x;
    if (idx >= K_DIM * N_OUT) return;
    int k = idx >> 11;       // / 2048
    int c = idx & 2047;
    float v;
    if (c < 768) {
        v = (k < 256) ? Wiou[k * 768 + c] : Waiou[(k - 256) * 768 + c];
    } else {
        int j = c - 768;
        v = (k < 256) ? 2.0f * Wf[k * 256 + (j & 255)]
                      : Waf[(k - 256) * 1280 + j];
    }
    g_Wp[idx] = __uint_as_float(f2tf32(v));   // pre-round B to tf32
}

// ---------------------------------------------------------------------------
__device__ __forceinline__ void load_tileA(const float* __restrict__ x,
                                           const float* __restrict__ x_mask,
                                           const float* __restrict__ nh,
                                           int rowbase, int k0, int tid,
                                           float4* ra)
{
#pragma unroll
    for (int i = 0; i < 2; i++) {
        int idx = i * 256 + tid;
        int r   = idx >> 2;
        int gk  = k0 + (idx & 3) * 4;
        int row = rowbase + r;
        float4 v = make_float4(0.f, 0.f, 0.f, 0.f);
        if (row < M_NODES) {
            if (gk < 256) {
                v = *(const float4*)(x + (size_t)row * 256 + gk);
                float m = x_mask[row];
                v.x *= m; v.y *= m; v.z *= m; v.w *= m;
            } else {
                v = *(const float4*)(nh + (size_t)row * 1280 + (gk - 256));
            }
        }
        ra[i] = v;
    }
}

__device__ __forceinline__ void load_tileB(int colbase, int k0, int tid, float4* rb)
{
#pragma unroll
    for (int i = 0; i < 2; i++) {
        int idx = i * 256 + tid;
        int kl  = idx >> 5;
        int n4  = (idx & 31) * 4;
        rb[i] = *(const float4*)(g_Wp + (size_t)(k0 + kl) * N_OUT + colbase + n4);
    }
}

__device__ __forceinline__ void store_tileA(float* sa, int tid, const float4* ra)
{
#pragma unroll
    for (int i = 0; i < 2; i++) {
        int idx = i * 256 + tid;
        int r   = idx >> 2;
        int kl  = (idx & 3) * 4;
        sa[(kl + 0) * SA + r] = __uint_as_float(f2tf32(ra[i].x));
        sa[(kl + 1) * SA + r] = __uint_as_float(f2tf32(ra[i].y));
        sa[(kl + 2) * SA + r] = __uint_as_float(f2tf32(ra[i].z));
        sa[(kl + 3) * SA + r] = __uint_as_float(f2tf32(ra[i].w));
    }
}

__device__ __forceinline__ void store_tileB(float* sb, int tid, const float4* rb)
{
#pragma unroll
    for (int i = 0; i < 2; i++) {
        int idx = i * 256 + tid;
        int kl  = idx >> 5;
        int n4  = (idx & 31) * 4;
        *(float4*)(sb + kl * SB + n4) = rb[i];
    }
}

// ---------------------------------------------------------------------------
__global__ __launch_bounds__(256, 2)
void gemm_tf32_kernel(const float* __restrict__ x,
                      const float* __restrict__ x_mask,
                      const float* __restrict__ nh)
{
    __shared__ float s_a[2][BK * SA];
    __shared__ float s_b[2][BK * SB];

    const int tid  = threadIdx.x;
    const int warp = tid >> 5;
    const int lane = tid & 31;
    const int gid  = lane >> 2;   // group id 0..7
    const int tig  = lane & 3;    // thread-in-group 0..3
    const int wm   = warp & 1;    // 2 warps over M (64 each)
    const int wn   = warp >> 1;   // 4 warps over N (32 each)

    const int rowbase = blockIdx.y * BM;
    const int colbase = blockIdx.x * BN;   // col tiles fastest -> A-tile L2 reuse

    float acc[4][4][4];
#pragma unroll
    for (int a = 0; a < 4; a++)
#pragma unroll
        for (int b = 0; b < 4; b++)
#pragma unroll
            for (int q = 0; q < 4; q++) acc[a][b][q] = 0.f;

    float4 ra[2], rb[2];

    // prologue: tile 0
    load_tileA(x, x_mask, nh, rowbase, 0, tid, ra);
    load_tileB(colbase, 0, tid, rb);
    store_tileA(s_a[0], tid, ra);
    store_tileB(s_b[0], tid, rb);
    __syncthreads();

    const int NT = K_DIM / BK;   // 96
    for (int kt = 0; kt < NT; kt++) {
        const int cur = kt & 1;
        if (kt + 1 < NT) {
            load_tileA(x, x_mask, nh, rowbase, (kt + 1) * BK, tid, ra);
            load_tileB(colbase, (kt + 1) * BK, tid, rb);
        }
        const float* sa = s_a[cur];
        const float* sb = s_b[cur];

#pragma unroll
        for (int ks = 0; ks < 2; ks++) {
            const int kk = ks * 8;
            uint32_t af[4][4], bf[4][2];
#pragma unroll
            for (int mt = 0; mt < 4; mt++) {
                int r0 = wm * 64 + mt * 16 + gid;
                const float* b0 = sa + (kk + tig) * SA;
                const float* b1 = sa + (kk + tig + 4) * SA;
                af[mt][0] = __float_as_uint(b0[r0]);
                af[mt][1] = __float_as_uint(b0[r0 + 8]);
                af[mt][2] = __float_as_uint(b1[r0]);
                af[mt][3] = __float_as_uint(b1[r0 + 8]);
            }
#pragma unroll
            for (int nt = 0; nt < 4; nt++) {
                int c0 = wn * 32 + nt * 8 + gid;
                bf[nt][0] = __float_as_uint(sb[(kk + tig) * SB + c0]);
                bf[nt][1] = __float_as_uint(sb[(kk + tig + 4) * SB + c0]);
            }
#pragma unroll
            for (int mt = 0; mt < 4; mt++)
#pragma unroll
                for (int nt = 0; nt < 4; nt++) {
                    asm volatile(
                        "mma.sync.aligned.m16n8k8.row.col.f32.tf32.tf32.f32 "
                        "{%0,%1,%2,%3}, {%4,%5,%6,%7}, {%8,%9}, {%0,%1,%2,%3};\n"
                        : "+f"(acc[mt][nt][0]), "+f"(acc[mt][nt][1]),
                          "+f"(acc[mt][nt][2]), "+f"(acc[mt][nt][3])
                        : "r"(af[mt][0]), "r"(af[mt][1]),
                          "r"(af[mt][2]), "r"(af[mt][3]),
                          "r"(bf[nt][0]), "r"(bf[nt][1]));
                }
        }

        if (kt + 1 < NT) {
            const int nxt = cur ^ 1;
            store_tileA(s_a[nxt], tid, ra);
            store_tileB(s_b[nxt], tid, rb);
            __syncthreads();
        }
    }

    // writeback
#pragma unroll
    for (int mt = 0; mt < 4; mt++) {
        int r0 = rowbase + wm * 64 + mt * 16 + gid;
#pragma unroll
        for (int nt = 0; nt < 4; nt++) {
            int c0 = colbase + wn * 32 + nt * 8 + tig * 2;
            if (r0 < M_NODES)
                *(float2*)(g_P + (size_t)r0 * N_OUT + c0) =
                    make_float2(acc[mt][nt][0], acc[mt][nt][1]);
            if (r0 + 8 < M_NODES)
                *(float2*)(g_P + (size_t)(r0 + 8) * N_OUT + c0) =
                    make_float2(acc[mt][nt][2], acc[mt][nt][3]);
        }
    }
}

// ---------------------------------------------------------------------------
__global__ void epilogue_kernel(const float* __restrict__ x_mask,
                                const float* __restrict__ nc,
                                const float* __restrict__ b_iou_in,
                                const float* __restrict__ b_f_in,
                                const float* __restrict__ b_aggr_iou,
                                const float* __restrict__ b_aggr_f,
                                float* __restrict__ out)
{
    const int n = blockIdx.x;
    const int j = threadIdx.x;
    const float m = x_mask[n];
    const float* row = g_P + (size_t)n * N_OUT;

    float iv = row[j]       + b_aggr_iou[j]       + m * b_iou_in[j];
    float ov = row[256 + j] + b_aggr_iou[256 + j] + m * b_iou_in[256 + j];
    float uv = row[512 + j] + b_aggr_iou[512 + j] + m * b_iou_in[512 + j];
    float fb = 2.0f * m * b_f_in[j];

    float cagg = 0.0f;
#pragma unroll
    for (int ch = 0; ch < NCH; ch++) {
        int o = ch * 256 + j;
        float fg = row[768 + o] + b_aggr_f[o] + fb;
        float f  = 1.0f / (1.0f + expf(-fg));
        cagg += f * nc[(size_t)n * (NCH * 256) + o];
    }

    float ig = 1.0f / (1.0f + expf(-iv));
    float og = 1.0f / (1.0f + expf(-ov));
    float ug = tanhf(uv);
    float c  = ig * ug + cagg;
    float h  = og * tanhf(c);

    out[(size_t)n * HDIM + j] = h;                                    // h block
    out[(size_t)M_NODES * HDIM + (size_t)n * HDIM + j] = c;           // c block
}

// ---------------------------------------------------------------------------
extern "C" void kernel_launch(void* const* d_in, const int* in_sizes, int n_in,
                              void* d_out, int out_size)
{
    const float* x      = (const float*)d_in[0];
    const float* x_mask = (const float*)d_in[1];
    const float* nh     = (const float*)d_in[2];
    const float* nc     = (const float*)d_in[3];
    const float* Wiou   = (const float*)d_in[4];
    const float* biou   = (const float*)d_in[5];
    const float* Wf     = (const float*)d_in[6];
    const float* bf     = (const float*)d_in[7];
    const float* Waiou  = (const float*)d_in[8];
    const float* baiou  = (const float*)d_in[9];
    const float* Waf    = (const float*)d_in[10];
    const float* baf    = (const float*)d_in[11];
    float* out = (float*)d_out;

    pack_w_kernel<<<(K_DIM * N_OUT + 255) / 256, 256>>>(Wiou, Wf, Waiou, Waf);

    dim3 grid(N_OUT / BN, (M_NODES + BM - 1) / BM);   // col tiles fastest
    gemm_tf32_kernel<<<grid, 256>>>(x, x_mask, nh);

    epilogue_kernel<<<M_NODES, 256>>>(x_mask, nc, biou, bf, baiou, baf, out);
}

// round 16
// speedup vs baseline: 1.0031x; 1.0012x over previous
#include <cuda_runtime.h>
#include <cstdint>

// ---------------------------------------------------------------------------
// TreeLSTMCell fused as ONE GEMM + epilogue.
//
//   A[n, 0:256]    = x[n] * x_mask[n]
//   A[n, 256:1536] = neighbour_h[n] (flattened 5*256)
//   W[k, c] packed:
//     c in [0,768):    k<256 -> W_iou_in[k,c]        else W_aggr_iou[k-256,c]
//     c in [768,2048): j=c-768
//                      k<256 -> 2*W_f_in[k, j%256]   else W_aggr_f[k-256, j]
//   P = A @ W   (tf32 tensor cores, fp32 accumulate)
//   Epilogue: add biases (mask-scaled where needed), gates, child reduction.
// ---------------------------------------------------------------------------

#define M_NODES 50000
#define K_DIM   1536
#define N_OUT   2048
#define HDIM    256
#define NCH     5

#define BM 128
#define BN 128
#define BK 16
#define SA 136   // padded smem stride (16-float skew -> conflict-free frag LDS)
#define SB 136

// Scratch (allocation-free rule: __device__ globals)
__device__ float g_Wp[K_DIM * N_OUT];                     // 12.6 MB packed weights (tf32-rounded)
__device__ float g_P[(size_t)M_NODES * N_OUT];            // 409.6 MB pre-activation scratch

// ---------------------------------------------------------------------------
__device__ __forceinline__ uint32_t f2tf32(float f) {
    uint32_t u;
    asm("cvt.rna.tf32.f32 %0, %1;" : "=r"(u) : "f"(f));
    return u;
}

// ---------------------------------------------------------------------------
__global__ void pack_w_kernel(const float* __restrict__ Wiou,
                              const float* __restrict__ Wf,
                              const float* __restrict__ Waiou,
                              const float* __restrict__ Waf)
{
    int idx = blockIdx.x * blockDim.x + threadIdx.x;
    if (idx >= K_DIM * N_OUT) return;
    int k = idx >> 11;       // / 2048
    int c = idx & 2047;
    float v;
    if (c < 768) {
        v = (k < 256) ? Wiou[k * 768 + c] : Waiou[(k - 256) * 768 + c];
    } else {
        int j = c - 768;
        v = (k < 256) ? 2.0f * Wf[k * 256 + (j & 255)]
                      : Waf[(k - 256) * 1280 + j];
    }
    g_Wp[idx] = __uint_as_float(f2tf32(v));   // pre-round B to tf32
}

// ---------------------------------------------------------------------------
__device__ __forceinline__ void load_tileA(const float* __restrict__ x,
                                           const float* __restrict__ x_mask,
                                           const float* __restrict__ nh,
                                           int rowbase, int k0, int tid,
                                           float4* ra)
{
#pragma unroll
    for (int i = 0; i < 2; i++) {
        int idx = i * 256 + tid;
        int r   = idx >> 2;
        int gk  = k0 + (idx & 3) * 4;
        int row = rowbase + r;
        float4 v = make_float4(0.f, 0.f, 0.f, 0.f);
        if (row < M_NODES) {
            if (gk < 256) {
                v = *(const float4*)(x + (size_t)row * 256 + gk);
                float m = x_mask[row];
                v.x *= m; v.y *= m; v.z *= m; v.w *= m;
            } else {
                v = *(const float4*)(nh + (size_t)row * 1280 + (gk - 256));
            }
        }
        ra[i] = v;
    }
}

__device__ __forceinline__ void load_tileB(int colbase, int k0, int tid, float4* rb)
{
#pragma unroll
    for (int i = 0; i < 2; i++) {
        int idx = i * 256 + tid;
        int kl  = idx >> 5;
        int n4  = (idx & 31) * 4;
        rb[i] = *(const float4*)(g_Wp + (size_t)(k0 + kl) * N_OUT + colbase + n4);
    }
}

__device__ __forceinline__ void store_tileA(float* sa, int tid, const float4* ra)
{
#pragma unroll
    for (int i = 0; i < 2; i++) {
        int idx = i * 256 + tid;
        int r   = idx >> 2;
        int kl  = (idx & 3) * 4;
        sa[(kl + 0) * SA + r] = __uint_as_float(f2tf32(ra[i].x));
        sa[(kl + 1) * SA + r] = __uint_as_float(f2tf32(ra[i].y));
        sa[(kl + 2) * SA + r] = __uint_as_float(f2tf32(ra[i].z));
        sa[(kl + 3) * SA + r] = __uint_as_float(f2tf32(ra[i].w));
    }
}

__device__ __forceinline__ void store_tileB(float* sb, int tid, const float4* rb)
{
#pragma unroll
    for (int i = 0; i < 2; i++) {
        int idx = i * 256 + tid;
        int kl  = idx >> 5;
        int n4  = (idx & 31) * 4;
        *(float4*)(sb + kl * SB + n4) = rb[i];
    }
}

// ---------------------------------------------------------------------------
__global__ __launch_bounds__(256, 2)
void gemm_tf32_kernel(const float* __restrict__ x,
                      const float* __restrict__ x_mask,
                      const float* __restrict__ nh)
{
    __shared__ float s_a[2][BK * SA];
    __shared__ float s_b[2][BK * SB];

    const int tid  = threadIdx.x;
    const int warp = tid >> 5;
    const int lane = tid & 31;
    const int gid  = lane >> 2;   // group id 0..7
    const int tig  = lane & 3;    // thread-in-group 0..3
    const int wm   = warp & 1;    // 2 warps over M (64 each)
    const int wn   = warp >> 1;   // 4 warps over N (32 each)

    const int rowbase = blockIdx.y * BM;
    const int colbase = blockIdx.x * BN;   // col tiles fastest -> A-tile L2 reuse

    float acc[4][4][4];
#pragma unroll
    for (int a = 0; a < 4; a++)
#pragma unroll
        for (int b = 0; b < 4; b++)
#pragma unroll
            for (int q = 0; q < 4; q++) acc[a][b][q] = 0.f;

    float4 ra[2], rb[2];

    // prologue: tile 0
    load_tileA(x, x_mask, nh, rowbase, 0, tid, ra);
    load_tileB(colbase, 0, tid, rb);
    store_tileA(s_a[0], tid, ra);
    store_tileB(s_b[0], tid, rb);
    __syncthreads();

    const int NT = K_DIM / BK;   // 96
    for (int kt = 0; kt < NT; kt++) {
        const int cur = kt & 1;
        if (kt + 1 < NT) {
            load_tileA(x, x_mask, nh, rowbase, (kt + 1) * BK, tid, ra);
            load_tileB(colbase, (kt + 1) * BK, tid, rb);
        }
        const float* sa = s_a[cur];
        const float* sb = s_b[cur];

#pragma unroll
        for (int ks = 0; ks < 2; ks++) {
            const int kk = ks * 8;
            uint32_t af[4][4], bf[4][2];
#pragma unroll
            for (int mt = 0; mt < 4; mt++) {
                int r0 = wm * 64 + mt * 16 + gid;
                const float* b0 = sa + (kk + tig) * SA;
                const float* b1 = sa + (kk + tig + 4) * SA;
                af[mt][0] = __float_as_uint(b0[r0]);
                af[mt][1] = __float_as_uint(b0[r0 + 8]);
                af[mt][2] = __float_as_uint(b1[r0]);
                af[mt][3] = __float_as_uint(b1[r0 + 8]);
            }
#pragma unroll
            for (int nt = 0; nt < 4; nt++) {
                int c0 = wn * 32 + nt * 8 + gid;
                bf[nt][0] = __float_as_uint(sb[(kk + tig) * SB + c0]);
                bf[nt][1] = __float_as_uint(sb[(kk + tig + 4) * SB + c0]);
            }
#pragma unroll
            for (int mt = 0; mt < 4; mt++)
#pragma unroll
                for (int nt = 0; nt < 4; nt++) {
                    asm volatile(
                        "mma.sync.aligned.m16n8k8.row.col.f32.tf32.tf32.f32 "
                        "{%0,%1,%2,%3}, {%4,%5,%6,%7}, {%8,%9}, {%0,%1,%2,%3};\n"
                        : "+f"(acc[mt][nt][0]), "+f"(acc[mt][nt][1]),
                          "+f"(acc[mt][nt][2]), "+f"(acc[mt][nt][3])
                        : "r"(af[mt][0]), "r"(af[mt][1]),
                          "r"(af[mt][2]), "r"(af[mt][3]),
                          "r"(bf[nt][0]), "r"(bf[nt][1]));
                }
        }

        if (kt + 1 < NT) {
            const int nxt = cur ^ 1;
            store_tileA(s_a[nxt], tid, ra);
            store_tileB(s_b[nxt], tid, rb);
            __syncthreads();
        }
    }

    // writeback
#pragma unroll
    for (int mt = 0; mt < 4; mt++) {
        int r0 = rowbase + wm * 64 + mt * 16 + gid;
#pragma unroll
        for (int nt = 0; nt < 4; nt++) {
            int c0 = colbase + wn * 32 + nt * 8 + tig * 2;
            if (r0 < M_NODES)
                *(float2*)(g_P + (size_t)r0 * N_OUT + c0) =
                    make_float2(acc[mt][nt][0], acc[mt][nt][1]);
            if (r0 + 8 < M_NODES)
                *(float2*)(g_P + (size_t)(r0 + 8) * N_OUT + c0) =
                    make_float2(acc[mt][nt][2], acc[mt][nt][3]);
        }
    }
}

// ---------------------------------------------------------------------------
__global__ void epilogue_kernel(const float* __restrict__ x_mask,
                                const float* __restrict__ nc,
                                const float* __restrict__ b_iou_in,
                                const float* __restrict__ b_f_in,
                                const float* __restrict__ b_aggr_iou,
                                const float* __restrict__ b_aggr_f,
                                float* __restrict__ out)
{
    const int n = blockIdx.x;
    const int j = threadIdx.x;
    const float m = x_mask[n];
    const float* row = g_P + (size_t)n * N_OUT;

    float iv = row[j]       + b_aggr_iou[j]       + m * b_iou_in[j];
    float ov = row[256 + j] + b_aggr_iou[256 + j] + m * b_iou_in[256 + j];
    float uv = row[512 + j] + b_aggr_iou[512 + j] + m * b_iou_in[512 + j];
    float fb = 2.0f * m * b_f_in[j];

    float cagg = 0.0f;
#pragma unroll
    for (int ch = 0; ch < NCH; ch++) {
        int o = ch * 256 + j;
        float fg = row[768 + o] + b_aggr_f[o] + fb;
        float f  = 1.0f / (1.0f + expf(-fg));
        cagg += f * nc[(size_t)n * (NCH * 256) + o];
    }

    float ig = 1.0f / (1.0f + expf(-iv));
    float og = 1.0f / (1.0f + expf(-ov));
    float ug = tanhf(uv);
    float c  = ig * ug + cagg;
    float h  = og * tanhf(c);

    out[(size_t)n * HDIM + j] = h;                                    // h block
    out[(size_t)M_NODES * HDIM + (size_t)n * HDIM + j] = c;           // c block
}

// ---------------------------------------------------------------------------
extern "C" void kernel_launch(void* const* d_in, const int* in_sizes, int n_in,
                              void* d_out, int out_size)
{
    const float* x      = (const float*)d_in[0];
    const float* x_mask = (const float*)d_in[1];
    const float* nh     = (const float*)d_in[2];
    const float* nc     = (const float*)d_in[3];
    const float* Wiou   = (const float*)d_in[4];
    const float* biou   = (const float*)d_in[5];
    const float* Wf     = (const float*)d_in[6];
    const float* bf     = (const float*)d_in[7];
    const float* Waiou  = (const float*)d_in[8];
    const float* baiou  = (const float*)d_in[9];
    const float* Waf    = (const float*)d_in[10];
    const float* baf    = (const float*)d_in[11];
    float* out = (float*)d_out;

    pack_w_kernel<<<(K_DIM * N_OUT + 255) / 256, 256>>>(Wiou, Wf, Waiou, Waf);

    dim3 grid(N_OUT / BN, (M_NODES + BM - 1) / BM);   // col tiles fastest
    gemm_tf32_kernel<<<grid, 256>>>(x, x_mask, nh);

    epilogue_kernel<<<M_NODES, 256>>>(x_mask, nc, biou, bf, baiou, baf, out);
}